// round 4
// baseline (speedup 1.0000x reference)
#include <cuda_runtime.h>
#include <cuda_fp16.h>
#include <cstdint>

// ============================================================================
// out[b,s,o] = gelu_tanh( (hs[b,s,:] . w_int8[o,:]) * w_scale[o] + bias[o] )
// Harness compiles at PTX target sm_103 (NO 'a' suffix) -> tcgen05 unusable.
// Fallback: Ampere-style mma.sync.m16n8k16 f16 kernel with cp.async pipeline.
//   A [8192,4096] f16 (prepass from f32), W [16384,4096] f16 (prepass, exact).
//   Tile 128x256xK64, 4-stage cp.async, 8 warps (2x4), warp tile 64x64.
//   Fused per-channel dequant + bias + tanh-GELU epilogue from registers.
// ============================================================================

static constexpr int MDIM = 8192;
static constexpr int KDIM = 4096;
static constexpr int NDIM = 16384;
static constexpr int TILE_M = 128;
static constexpr int TILE_N = 256;
static constexpr int KCHUNK = 64;                 // 128 bytes/row = SW128 atom
static constexpr int NCHUNKS = KDIM / KCHUNK;     // 64
static constexpr int NSTAGES = 4;
static constexpr uint32_t A_STAGE_BYTES = TILE_M * 128;   // 16384
static constexpr uint32_t B_STAGE_BYTES = TILE_N * 128;   // 32768
static constexpr uint32_t STAGE_BYTES = A_STAGE_BYTES + B_STAGE_BYTES; // 49152
static constexpr uint32_t SMEM_TOTAL = NSTAGES * STAGE_BYTES;          // 196608

static constexpr int NT_M = MDIM / TILE_M;  // 64
static constexpr int NT_N = NDIM / TILE_N;  // 64
static constexpr int GRID = NT_M * NT_N;    // 4096
static constexpr int GM = 16;               // M-supertile for L2 reuse

__device__ __align__(1024) __half g_A[(size_t)MDIM * KDIM];   // 64 MB
__device__ __align__(1024) __half g_W[(size_t)NDIM * KDIM];   // 128 MB

// ---------------------------------------------------------------------------
__device__ __forceinline__ uint32_t smem_u32(const void* p) {
    uint32_t a;
    asm("{ .reg .u64 t; cvta.to.shared.u64 t, %1; cvt.u32.u64 %0, t; }"
        : "=r"(a) : "l"(p));
    return a;
}

#define SW128(o) ((o) ^ (((o) >> 3) & 0x70))

#define CP_ASYNC16(saddr, gaddr) \
    asm volatile("cp.async.cg.shared.global [%0], [%1], 16;" :: "r"(saddr), "l"(gaddr))
#define CP_COMMIT() asm volatile("cp.async.commit_group;" ::: "memory")
#define CP_WAIT3()  asm volatile("cp.async.wait_group 3;" ::: "memory")

#define LDSM_X4(r0, r1, r2, r3, addr)                                          \
    asm volatile("ldmatrix.sync.aligned.m8n8.x4.shared.b16 {%0,%1,%2,%3}, [%4];" \
        : "=r"(r0), "=r"(r1), "=r"(r2), "=r"(r3) : "r"(addr))

#define MMA16816(c, a0, a1, a2, a3, b0, b1)                                    \
    asm volatile("mma.sync.aligned.m16n8k16.row.col.f32.f16.f16.f32 "          \
        "{%0,%1,%2,%3}, {%4,%5,%6,%7}, {%8,%9}, {%0,%1,%2,%3};"                \
        : "+f"((c)[0]), "+f"((c)[1]), "+f"((c)[2]), "+f"((c)[3])               \
        : "r"(a0), "r"(a1), "r"(a2), "r"(a3), "r"(b0), "r"(b1))

// ---------------------------------------------------------------------------
// Prepasses
// ---------------------------------------------------------------------------
__global__ void __launch_bounds__(256) cvt_a_kernel(const float* __restrict__ in) {
    size_t i = ((size_t)blockIdx.x * blockDim.x + threadIdx.x) * 8;
    float4 f0 = *reinterpret_cast<const float4*>(in + i);
    float4 f1 = *reinterpret_cast<const float4*>(in + i + 4);
    __half2 h[4];
    h[0] = __floats2half2_rn(f0.x, f0.y);
    h[1] = __floats2half2_rn(f0.z, f0.w);
    h[2] = __floats2half2_rn(f1.x, f1.y);
    h[3] = __floats2half2_rn(f1.z, f1.w);
    *reinterpret_cast<uint4*>(g_A + i) = *reinterpret_cast<uint4*>(h);
}

__global__ void __launch_bounds__(256) cvt_w_kernel(const int* __restrict__ in) {
    size_t i = ((size_t)blockIdx.x * blockDim.x + threadIdx.x) * 8;
    int4 w0 = *reinterpret_cast<const int4*>(in + i);
    int4 w1 = *reinterpret_cast<const int4*>(in + i + 4);
    __half2 h[4];
    h[0] = __halves2half2(__int2half_rn(w0.x), __int2half_rn(w0.y));
    h[1] = __halves2half2(__int2half_rn(w0.z), __int2half_rn(w0.w));
    h[2] = __halves2half2(__int2half_rn(w1.x), __int2half_rn(w1.y));
    h[3] = __halves2half2(__int2half_rn(w1.z), __int2half_rn(w1.w));
    *reinterpret_cast<uint4*>(g_W + i) = *reinterpret_cast<uint4*>(h);
}

__device__ __forceinline__ float tanh_ex(float x) {
    return 1.0f - 2.0f / (1.0f + __expf(2.0f * x));
}
__device__ __forceinline__ float gelu_f(float y) {
    float inner = 0.7978845608028654f * fmaf(0.044715f * y * y, y, y);
    return 0.5f * y * (1.0f + tanh_ex(inner));
}

// ---------------------------------------------------------------------------
// GEMM kernel: mma.sync m16n8k16, 256 threads, warp grid 2(m) x 4(n)
// ---------------------------------------------------------------------------
__global__ void __launch_bounds__(256, 1) gemm_kernel(
    const float* __restrict__ w_scale,
    const float* __restrict__ bias,
    float* __restrict__ out
) {
    extern __shared__ __align__(1024) char smem[];
    const uint32_t sbase = smem_u32(smem);
    const int tid = threadIdx.x;
    const int lane = tid & 31;
    const int wid = tid >> 5;
    const int wm = wid >> 2;        // 0..1 -> m offset wm*64
    const int wn = wid & 3;         // 0..3 -> n offset wn*64

    // Supertiled rasterization for L2 reuse
    const int bid = blockIdx.x;
    const int tpg = GM * NT_N;
    const int g = bid / tpg;
    const int r = bid % tpg;
    const int mi = g * GM + (r % GM);
    const int ni = r / GM;
    const int m0 = mi * TILE_M;
    const int n0 = ni * TILE_N;

    // per-thread cp.async source/dest precompute: 12 segs (4 A + 8 B)
    const int ld_row_a = tid >> 3;          // 0..31 (A: +i*32 rows)
    const int ld_j = tid & 7;               // 16B seg within 128B row
    // ldmatrix addressing
    const int lg = lane >> 3;               // group 0..3
    const int rin = lane & 7;

    // fragment smem base addresses (lane-dependent, stage-independent parts)
    // A: row = wm*64 + sm*16 + (lg&1)*8 + rin ; j = kk*2 + (lg>>1)
    // B: row = wn*64 + sn2*16 + (lg>>1)*8 + rin ; j = kk*2 + (lg&1)
    const uint32_t a_row_base = (uint32_t)(wm * 64 + (lg & 1) * 8 + rin);
    const uint32_t b_row_base = (uint32_t)(wn * 64 + (lg >> 1) * 8 + rin);
    const uint32_t a_jbase = (uint32_t)(lg >> 1);
    const uint32_t b_jbase = (uint32_t)(lg & 1);

    float c[4][8][4];
    #pragma unroll
    for (int i = 0; i < 4; ++i)
        #pragma unroll
        for (int j = 0; j < 8; ++j)
            #pragma unroll
            for (int q = 0; q < 4; ++q) c[i][j][q] = 0.0f;

    // ---------------- load helper (as lambda) ----------------
    auto load_chunk = [&](int k, int s) {
        const uint32_t stage = sbase + (uint32_t)s * STAGE_BYTES;
        const size_t k0 = (size_t)k * KCHUNK;
        #pragma unroll
        for (int i = 0; i < 4; ++i) {
            int row = ld_row_a + i * 32;
            uint32_t off = (uint32_t)(row * 128 + ld_j * 16);
            const __half* src = g_A + (size_t)(m0 + row) * KDIM + k0 + ld_j * 8;
            CP_ASYNC16(stage + SW128(off), src);
        }
        #pragma unroll
        for (int i = 0; i < 8; ++i) {
            int row = ld_row_a + i * 32;
            uint32_t off = (uint32_t)(row * 128 + ld_j * 16);
            const __half* src = g_W + (size_t)(n0 + row) * KDIM + k0 + ld_j * 8;
            CP_ASYNC16(stage + A_STAGE_BYTES + SW128(off), src);
        }
    };

    // ---------------- prologue: fill pipeline ----------------
    #pragma unroll
    for (int s = 0; s < NSTAGES; ++s) {
        load_chunk(s, s);
        CP_COMMIT();
    }

    // ---------------- main loop ----------------
    for (int k = 0; k < NCHUNKS; ++k) {
        CP_WAIT3();          // chunk k resident (empty tail commits keep parity)
        __syncthreads();

        const uint32_t stage = sbase + (uint32_t)(k % NSTAGES) * STAGE_BYTES;
        const uint32_t sA = stage;
        const uint32_t sB = stage + A_STAGE_BYTES;

        #pragma unroll
        for (int kk = 0; kk < 4; ++kk) {
            // A fragments: 4 m-subtiles
            uint32_t a[4][4];
            #pragma unroll
            for (int sm = 0; sm < 4; ++sm) {
                uint32_t row = a_row_base + sm * 16;
                uint32_t j = a_jbase + kk * 2;
                uint32_t addr = sA + row * 128 + (((j ^ (row & 7)) & 7) << 4);
                LDSM_X4(a[sm][0], a[sm][1], a[sm][2], a[sm][3], addr);
            }
            // B fragments: 4 n16-subtiles -> 8 n8 subtiles
            uint32_t b[8][2];
            #pragma unroll
            for (int sn2 = 0; sn2 < 4; ++sn2) {
                uint32_t row = b_row_base + sn2 * 16;
                uint32_t j = b_jbase + kk * 2;
                uint32_t addr = sB + row * 128 + (((j ^ (row & 7)) & 7) << 4);
                uint32_t r0, r1, r2, r3;
                LDSM_X4(r0, r1, r2, r3, addr);
                b[sn2 * 2][0] = r0; b[sn2 * 2][1] = r1;
                b[sn2 * 2 + 1][0] = r2; b[sn2 * 2 + 1][1] = r3;
            }
            #pragma unroll
            for (int sm = 0; sm < 4; ++sm)
                #pragma unroll
                for (int sn = 0; sn < 8; ++sn)
                    MMA16816(c[sm][sn], a[sm][0], a[sm][1], a[sm][2], a[sm][3],
                             b[sn][0], b[sn][1]);
        }

        __syncthreads();
        if (k + NSTAGES < NCHUNKS) load_chunk(k + NSTAGES, k % NSTAGES);
        CP_COMMIT();         // empty group OK: keeps wait_group parity uniform
    }

    // ---------------- epilogue ----------------
    const int col_q = 2 * (lane & 3);
    const int row_q = lane >> 2;
    #pragma unroll
    for (int sm = 0; sm < 4; ++sm) {
        const int row0 = m0 + wm * 64 + sm * 16 + row_q;
        const int row1 = row0 + 8;
        #pragma unroll
        for (int sn = 0; sn < 8; ++sn) {
            const int col = n0 + wn * 64 + sn * 8 + col_q;
            const float2 sc = *reinterpret_cast<const float2*>(w_scale + col);
            const float2 bi = *reinterpret_cast<const float2*>(bias + col);
            float y0 = fmaf(c[sm][sn][0], sc.x, bi.x);
            float y1 = fmaf(c[sm][sn][1], sc.y, bi.y);
            float y2 = fmaf(c[sm][sn][2], sc.x, bi.x);
            float y3 = fmaf(c[sm][sn][3], sc.y, bi.y);
            float2 v0 = make_float2(gelu_f(y0), gelu_f(y1));
            float2 v1 = make_float2(gelu_f(y2), gelu_f(y3));
            *reinterpret_cast<float2*>(out + (size_t)row0 * NDIM + col) = v0;
            *reinterpret_cast<float2*>(out + (size_t)row1 * NDIM + col) = v1;
        }
    }
}

// ---------------------------------------------------------------------------
extern "C" void kernel_launch(void* const* d_in, const int* in_sizes, int n_in,
                              void* d_out, int out_size) {
    (void)in_sizes; (void)n_in; (void)out_size;
    const float* hs = (const float*)d_in[0];
    const int* w_int8 = (const int*)d_in[1];
    const float* w_scale = (const float*)d_in[2];
    const float* bias = (const float*)d_in[3];
    float* out = (float*)d_out;

    cudaFuncSetAttribute(gemm_kernel,
                         cudaFuncAttributeMaxDynamicSharedMemorySize, SMEM_TOTAL);

    size_t nA = (size_t)MDIM * KDIM;
    cvt_a_kernel<<<(unsigned)(nA / 8 / 256), 256>>>(hs);
    size_t nW = (size_t)NDIM * KDIM;
    cvt_w_kernel<<<(unsigned)(nW / 8 / 256), 256>>>(w_int8);

    gemm_kernel<<<GRID, 256, SMEM_TOTAL>>>(w_scale, bias, out);
}

// round 5
// speedup vs baseline: 1.0241x; 1.0241x over previous
#include <cuda_runtime.h>
#include <cuda_fp16.h>
#include <cstdint>

// ============================================================================
// out[b,s,o] = gelu_tanh( (hs[b,s,:] . w_int8[o,:]) * w_scale[o] + bias[o] )
// sm_103 (no 'a') PTX target -> tcgen05 unavailable; mma.sync.m16n8k16 path.
//   Prepass (single kernel): A f32->f16, W i32->f16 (exact) into device globals.
//   GEMM: tile 128x256xK64, 4-stage cp.async (1 sync/iter, CUTLASS schedule),
//   8 warps (2x4), warp tile 64x64, intra-chunk LDSM double-buffering,
//   fused per-channel dequant + bias + tanh-GELU epilogue.
// ============================================================================

static constexpr int MDIM = 8192;
static constexpr int KDIM = 4096;
static constexpr int NDIM = 16384;
static constexpr int TILE_M = 128;
static constexpr int TILE_N = 256;
static constexpr int KCHUNK = 64;                 // 128 bytes/row = SW128 atom
static constexpr int NCHUNKS = KDIM / KCHUNK;     // 64
static constexpr int NSTAGES = 4;
static constexpr uint32_t A_STAGE_BYTES = TILE_M * 128;   // 16384
static constexpr uint32_t B_STAGE_BYTES = TILE_N * 128;   // 32768
static constexpr uint32_t STAGE_BYTES = A_STAGE_BYTES + B_STAGE_BYTES; // 49152
static constexpr uint32_t SMEM_TOTAL = NSTAGES * STAGE_BYTES;          // 196608

static constexpr int NT_M = MDIM / TILE_M;  // 64
static constexpr int NT_N = NDIM / TILE_N;  // 64
static constexpr int GRID = NT_M * NT_N;    // 4096
static constexpr int GM = 16;               // M-supertile for L2 reuse

__device__ __align__(1024) __half g_A[(size_t)MDIM * KDIM];   // 64 MB
__device__ __align__(1024) __half g_W[(size_t)NDIM * KDIM];   // 128 MB

// ---------------------------------------------------------------------------
__device__ __forceinline__ uint32_t smem_u32(const void* p) {
    uint32_t a;
    asm("{ .reg .u64 t; cvta.to.shared.u64 t, %1; cvt.u32.u64 %0, t; }"
        : "=r"(a) : "l"(p));
    return a;
}

#define SW128(o) ((o) ^ (((o) >> 3) & 0x70))

#define CP_ASYNC16(saddr, gaddr) \
    asm volatile("cp.async.cg.shared.global [%0], [%1], 16;" :: "r"(saddr), "l"(gaddr))
#define CP_COMMIT() asm volatile("cp.async.commit_group;" ::: "memory")
#define CP_WAIT2()  asm volatile("cp.async.wait_group 2;" ::: "memory")

#define LDSM_X4(r0, r1, r2, r3, addr)                                          \
    asm volatile("ldmatrix.sync.aligned.m8n8.x4.shared.b16 {%0,%1,%2,%3}, [%4];" \
        : "=r"(r0), "=r"(r1), "=r"(r2), "=r"(r3) : "r"(addr))

#define MMA16816(c, a0, a1, a2, a3, b0, b1)                                    \
    asm volatile("mma.sync.aligned.m16n8k16.row.col.f32.f16.f16.f32 "          \
        "{%0,%1,%2,%3}, {%4,%5,%6,%7}, {%8,%9}, {%0,%1,%2,%3};"                \
        : "+f"((c)[0]), "+f"((c)[1]), "+f"((c)[2]), "+f"((c)[3])               \
        : "r"(a0), "r"(a1), "r"(a2), "r"(a3), "r"(b0), "r"(b1))

// ---------------------------------------------------------------------------
// Merged prepass: blocks [0, GRID_A) convert A, rest convert W.
// ---------------------------------------------------------------------------
static constexpr unsigned GRID_A = (unsigned)((size_t)MDIM * KDIM / 8 / 256);  // 16384
static constexpr unsigned GRID_W = (unsigned)((size_t)NDIM * KDIM / 8 / 256);  // 32768

__global__ void __launch_bounds__(256) cvt_kernel(const float* __restrict__ a_in,
                                                  const int* __restrict__ w_in) {
    if (blockIdx.x < GRID_A) {
        size_t i = ((size_t)blockIdx.x * 256 + threadIdx.x) * 8;
        float4 f0 = *reinterpret_cast<const float4*>(a_in + i);
        float4 f1 = *reinterpret_cast<const float4*>(a_in + i + 4);
        __half2 h[4];
        h[0] = __floats2half2_rn(f0.x, f0.y);
        h[1] = __floats2half2_rn(f0.z, f0.w);
        h[2] = __floats2half2_rn(f1.x, f1.y);
        h[3] = __floats2half2_rn(f1.z, f1.w);
        *reinterpret_cast<uint4*>(g_A + i) = *reinterpret_cast<uint4*>(h);
    } else {
        size_t i = ((size_t)(blockIdx.x - GRID_A) * 256 + threadIdx.x) * 8;
        int4 w0 = *reinterpret_cast<const int4*>(w_in + i);
        int4 w1 = *reinterpret_cast<const int4*>(w_in + i + 4);
        __half2 h[4];
        h[0] = __halves2half2(__int2half_rn(w0.x), __int2half_rn(w0.y));
        h[1] = __halves2half2(__int2half_rn(w0.z), __int2half_rn(w0.w));
        h[2] = __halves2half2(__int2half_rn(w1.x), __int2half_rn(w1.y));
        h[3] = __halves2half2(__int2half_rn(w1.z), __int2half_rn(w1.w));
        *reinterpret_cast<uint4*>(g_W + i) = *reinterpret_cast<uint4*>(h);
    }
}

__device__ __forceinline__ float tanh_ex(float x) {
    return 1.0f - 2.0f / (1.0f + __expf(2.0f * x));
}
__device__ __forceinline__ float gelu_f(float y) {
    float inner = 0.7978845608028654f * fmaf(0.044715f * y * y, y, y);
    return 0.5f * y * (1.0f + tanh_ex(inner));
}

// ---------------------------------------------------------------------------
// GEMM kernel
// ---------------------------------------------------------------------------
__global__ void __launch_bounds__(256, 1) gemm_kernel(
    const float* __restrict__ w_scale,
    const float* __restrict__ bias,
    float* __restrict__ out
) {
    extern __shared__ __align__(1024) char smem[];
    const uint32_t sbase = smem_u32(smem);
    const int tid = threadIdx.x;
    const int lane = tid & 31;
    const int wid = tid >> 5;
    const int wm = wid >> 2;        // 0..1 -> m offset wm*64
    const int wn = wid & 3;         // 0..3 -> n offset wn*64

    // Supertiled rasterization for L2 reuse
    const int bid = blockIdx.x;
    const int tpg = GM * NT_N;
    const int g = bid / tpg;
    const int r = bid % tpg;
    const int mi = g * GM + (r % GM);
    const int ni = r / GM;
    const int m0 = mi * TILE_M;
    const int n0 = ni * TILE_N;

    const int ld_row_a = tid >> 3;          // 0..31
    const int ld_j = tid & 7;               // 16B seg within 128B row
    const int lg = lane >> 3;               // ldmatrix group 0..3
    const int rin = lane & 7;

    // fragment smem addressing (verified layout from R3)
    const uint32_t a_row_base = (uint32_t)(wm * 64 + (lg & 1) * 8 + rin);
    const uint32_t b_row_base = (uint32_t)(wn * 64 + (lg >> 1) * 8 + rin);
    const uint32_t a_jbase = (uint32_t)(lg >> 1);
    const uint32_t b_jbase = (uint32_t)(lg & 1);

    float c[4][8][4];
    #pragma unroll
    for (int i = 0; i < 4; ++i)
        #pragma unroll
        for (int j = 0; j < 8; ++j)
            #pragma unroll
            for (int q = 0; q < 4; ++q) c[i][j][q] = 0.0f;

    auto load_chunk = [&](int k, int s) {
        const uint32_t stage = sbase + (uint32_t)s * STAGE_BYTES;
        const size_t k0 = (size_t)k * KCHUNK;
        #pragma unroll
        for (int i = 0; i < 4; ++i) {
            int row = ld_row_a + i * 32;
            uint32_t off = (uint32_t)(row * 128 + ld_j * 16);
            const __half* src = g_A + (size_t)(m0 + row) * KDIM + k0 + ld_j * 8;
            CP_ASYNC16(stage + SW128(off), src);
        }
        #pragma unroll
        for (int i = 0; i < 8; ++i) {
            int row = ld_row_a + i * 32;
            uint32_t off = (uint32_t)(row * 128 + ld_j * 16);
            const __half* src = g_W + (size_t)(n0 + row) * KDIM + k0 + ld_j * 8;
            CP_ASYNC16(stage + A_STAGE_BYTES + SW128(off), src);
        }
    };

    // ---------------- prologue: fill 3 of 4 stages ----------------
    #pragma unroll
    for (int s = 0; s < NSTAGES - 1; ++s) {
        load_chunk(s, s);
        CP_COMMIT();
    }

    // ---------------- main loop: 1 sync/iter ----------------
    for (int k = 0; k < NCHUNKS; ++k) {
        CP_WAIT2();          // 3 groups in flight; oldest (chunk k) now resident
        __syncthreads();     // everyone done reading stage (k-1)%4 == (k+3)%4

        if (k + NSTAGES - 1 < NCHUNKS) load_chunk(k + NSTAGES - 1, (k + NSTAGES - 1) & 3);
        CP_COMMIT();         // always commit: uniform group parity

        const uint32_t sA = sbase + (uint32_t)(k & 3) * STAGE_BYTES;
        const uint32_t sB = sA + A_STAGE_BYTES;

        // intra-chunk fragment double buffering over kk = 0..3
        uint32_t a[2][4][4], b[2][8][2];

        auto load_frags = [&](int kk, int buf) {
            #pragma unroll
            for (int sm = 0; sm < 4; ++sm) {
                uint32_t row = a_row_base + sm * 16;
                uint32_t j = a_jbase + kk * 2;
                uint32_t addr = sA + row * 128 + (((j ^ (row & 7)) & 7) << 4);
                LDSM_X4(a[buf][sm][0], a[buf][sm][1], a[buf][sm][2], a[buf][sm][3], addr);
            }
            #pragma unroll
            for (int sn2 = 0; sn2 < 4; ++sn2) {
                uint32_t row = b_row_base + sn2 * 16;
                uint32_t j = b_jbase + kk * 2;
                uint32_t addr = sB + row * 128 + (((j ^ (row & 7)) & 7) << 4);
                uint32_t r0, r1, r2, r3;
                LDSM_X4(r0, r1, r2, r3, addr);
                b[buf][sn2 * 2][0] = r0;     b[buf][sn2 * 2][1] = r1;
                b[buf][sn2 * 2 + 1][0] = r2; b[buf][sn2 * 2 + 1][1] = r3;
            }
        };

        load_frags(0, 0);
        #pragma unroll
        for (int kk = 0; kk < 4; ++kk) {
            const int cur = kk & 1;
            if (kk < 3) load_frags(kk + 1, cur ^ 1);
            #pragma unroll
            for (int sm = 0; sm < 4; ++sm)
                #pragma unroll
                for (int sn = 0; sn < 8; ++sn)
                    MMA16816(c[sm][sn],
                             a[cur][sm][0], a[cur][sm][1], a[cur][sm][2], a[cur][sm][3],
                             b[cur][sn][0], b[cur][sn][1]);
        }
    }

    // ---------------- epilogue ----------------
    const int col_q = 2 * (lane & 3);
    const int row_q = lane >> 2;
    float2 sc[8], bi[8];
    #pragma unroll
    for (int sn = 0; sn < 8; ++sn) {
        const int col = n0 + wn * 64 + sn * 8 + col_q;
        sc[sn] = *reinterpret_cast<const float2*>(w_scale + col);
        bi[sn] = *reinterpret_cast<const float2*>(bias + col);
    }
    #pragma unroll
    for (int sm = 0; sm < 4; ++sm) {
        const int row0 = m0 + wm * 64 + sm * 16 + row_q;
        const int row1 = row0 + 8;
        #pragma unroll
        for (int sn = 0; sn < 8; ++sn) {
            const int col = n0 + wn * 64 + sn * 8 + col_q;
            float y0 = fmaf(c[sm][sn][0], sc[sn].x, bi[sn].x);
            float y1 = fmaf(c[sm][sn][1], sc[sn].y, bi[sn].y);
            float y2 = fmaf(c[sm][sn][2], sc[sn].x, bi[sn].x);
            float y3 = fmaf(c[sm][sn][3], sc[sn].y, bi[sn].y);
            float2 v0 = make_float2(gelu_f(y0), gelu_f(y1));
            float2 v1 = make_float2(gelu_f(y2), gelu_f(y3));
            *reinterpret_cast<float2*>(out + (size_t)row0 * NDIM + col) = v0;
            *reinterpret_cast<float2*>(out + (size_t)row1 * NDIM + col) = v1;
        }
    }
}

// ---------------------------------------------------------------------------
extern "C" void kernel_launch(void* const* d_in, const int* in_sizes, int n_in,
                              void* d_out, int out_size) {
    (void)in_sizes; (void)n_in; (void)out_size;
    const float* hs = (const float*)d_in[0];
    const int* w_int8 = (const int*)d_in[1];
    const float* w_scale = (const float*)d_in[2];
    const float* bias = (const float*)d_in[3];
    float* out = (float*)d_out;

    cudaFuncSetAttribute(gemm_kernel,
                         cudaFuncAttributeMaxDynamicSharedMemorySize, SMEM_TOTAL);

    cvt_kernel<<<GRID_A + GRID_W, 256>>>(hs, w_int8);
    gemm_kernel<<<GRID, 256, SMEM_TOTAL>>>(w_scale, bias, out);
}

// round 6
// speedup vs baseline: 1.0375x; 1.0131x over previous
#include <cuda_runtime.h>
#include <cuda_fp16.h>
#include <cstdint>

// ============================================================================
// out[b,s,o] = gelu_tanh( (hs[b,s,:] . w_int8[o,:]) * w_scale[o] + bias[o] )
// sm_103 (no 'a') PTX target -> tcgen05 unavailable; mma.sync.m16n8k16 path.
//   Prepass (single kernel): A f32->f16, W i32->f16 (exact) into device globals.
//   GEMM: tile 128x256xK64, 4-stage cp.async, 8 warps (2x4), warp tile 64x64.
//   R5: tail-positioned sync + cross-chunk fragment prefetch -> barrier-free
//   chunk head, LDSM latency hidden under kk=3 MMA block.
// ============================================================================

static constexpr int MDIM = 8192;
static constexpr int KDIM = 4096;
static constexpr int NDIM = 16384;
static constexpr int TILE_M = 128;
static constexpr int TILE_N = 256;
static constexpr int KCHUNK = 64;                 // 128 bytes/row = SW128 atom
static constexpr int NCHUNKS = KDIM / KCHUNK;     // 64
static constexpr int NSTAGES = 4;
static constexpr uint32_t A_STAGE_BYTES = TILE_M * 128;   // 16384
static constexpr uint32_t B_STAGE_BYTES = TILE_N * 128;   // 32768
static constexpr uint32_t STAGE_BYTES = A_STAGE_BYTES + B_STAGE_BYTES; // 49152
static constexpr uint32_t SMEM_TOTAL = NSTAGES * STAGE_BYTES;          // 196608

static constexpr int NT_M = MDIM / TILE_M;  // 64
static constexpr int NT_N = NDIM / TILE_N;  // 64
static constexpr int GRID = NT_M * NT_N;    // 4096
static constexpr int GM = 16;               // M-supertile for L2 reuse

__device__ __align__(1024) __half g_A[(size_t)MDIM * KDIM];   // 64 MB
__device__ __align__(1024) __half g_W[(size_t)NDIM * KDIM];   // 128 MB

// ---------------------------------------------------------------------------
__device__ __forceinline__ uint32_t smem_u32(const void* p) {
    uint32_t a;
    asm("{ .reg .u64 t; cvta.to.shared.u64 t, %1; cvt.u32.u64 %0, t; }"
        : "=r"(a) : "l"(p));
    return a;
}

#define SW128(o) ((o) ^ (((o) >> 3) & 0x70))

#define CP_ASYNC16(saddr, gaddr) \
    asm volatile("cp.async.cg.shared.global [%0], [%1], 16;" :: "r"(saddr), "l"(gaddr))
#define CP_COMMIT() asm volatile("cp.async.commit_group;" ::: "memory")
#define CP_WAIT2()  asm volatile("cp.async.wait_group 2;" ::: "memory")
#define CP_WAIT1()  asm volatile("cp.async.wait_group 1;" ::: "memory")

#define LDSM_X4(r0, r1, r2, r3, addr)                                          \
    asm volatile("ldmatrix.sync.aligned.m8n8.x4.shared.b16 {%0,%1,%2,%3}, [%4];" \
        : "=r"(r0), "=r"(r1), "=r"(r2), "=r"(r3) : "r"(addr))

#define MMA16816(c, a0, a1, a2, a3, b0, b1)                                    \
    asm volatile("mma.sync.aligned.m16n8k16.row.col.f32.f16.f16.f32 "          \
        "{%0,%1,%2,%3}, {%4,%5,%6,%7}, {%8,%9}, {%0,%1,%2,%3};"                \
        : "+f"((c)[0]), "+f"((c)[1]), "+f"((c)[2]), "+f"((c)[3])               \
        : "r"(a0), "r"(a1), "r"(a2), "r"(a3), "r"(b0), "r"(b1))

// ---------------------------------------------------------------------------
// Merged prepass: blocks [0, GRID_A) convert A, rest convert W.
// ---------------------------------------------------------------------------
static constexpr unsigned GRID_A = (unsigned)((size_t)MDIM * KDIM / 8 / 256);  // 16384
static constexpr unsigned GRID_W = (unsigned)((size_t)NDIM * KDIM / 8 / 256);  // 32768

__global__ void __launch_bounds__(256) cvt_kernel(const float* __restrict__ a_in,
                                                  const int* __restrict__ w_in) {
    if (blockIdx.x < GRID_A) {
        size_t i = ((size_t)blockIdx.x * 256 + threadIdx.x) * 8;
        float4 f0 = *reinterpret_cast<const float4*>(a_in + i);
        float4 f1 = *reinterpret_cast<const float4*>(a_in + i + 4);
        __half2 h[4];
        h[0] = __floats2half2_rn(f0.x, f0.y);
        h[1] = __floats2half2_rn(f0.z, f0.w);
        h[2] = __floats2half2_rn(f1.x, f1.y);
        h[3] = __floats2half2_rn(f1.z, f1.w);
        *reinterpret_cast<uint4*>(g_A + i) = *reinterpret_cast<uint4*>(h);
    } else {
        size_t i = ((size_t)(blockIdx.x - GRID_A) * 256 + threadIdx.x) * 8;
        int4 w0 = *reinterpret_cast<const int4*>(w_in + i);
        int4 w1 = *reinterpret_cast<const int4*>(w_in + i + 4);
        __half2 h[4];
        h[0] = __halves2half2(__int2half_rn(w0.x), __int2half_rn(w0.y));
        h[1] = __halves2half2(__int2half_rn(w0.z), __int2half_rn(w0.w));
        h[2] = __halves2half2(__int2half_rn(w1.x), __int2half_rn(w1.y));
        h[3] = __halves2half2(__int2half_rn(w1.z), __int2half_rn(w1.w));
        *reinterpret_cast<uint4*>(g_W + i) = *reinterpret_cast<uint4*>(h);
    }
}

__device__ __forceinline__ float tanh_ex(float x) {
    return 1.0f - 2.0f / (1.0f + __expf(2.0f * x));
}
__device__ __forceinline__ float gelu_f(float y) {
    float inner = 0.7978845608028654f * fmaf(0.044715f * y * y, y, y);
    return 0.5f * y * (1.0f + tanh_ex(inner));
}

// ---------------------------------------------------------------------------
// GEMM kernel
// ---------------------------------------------------------------------------
__global__ void __launch_bounds__(256, 1) gemm_kernel(
    const float* __restrict__ w_scale,
    const float* __restrict__ bias,
    float* __restrict__ out
) {
    extern __shared__ __align__(1024) char smem[];
    const uint32_t sbase = smem_u32(smem);
    const int tid = threadIdx.x;
    const int lane = tid & 31;
    const int wid = tid >> 5;
    const int wm = wid >> 2;        // 0..1 -> m offset wm*64
    const int wn = wid & 3;         // 0..3 -> n offset wn*64

    // Supertiled rasterization for L2 reuse
    const int bid = blockIdx.x;
    const int tpg = GM * NT_N;
    const int g = bid / tpg;
    const int r = bid % tpg;
    const int mi = g * GM + (r % GM);
    const int ni = r / GM;
    const int m0 = mi * TILE_M;
    const int n0 = ni * TILE_N;

    const int ld_row_a = tid >> 3;          // 0..31
    const int ld_j = tid & 7;               // 16B seg within 128B row
    const int lg = lane >> 3;               // ldmatrix group 0..3
    const int rin = lane & 7;

    // fragment smem addressing (verified layout, R3/R4)
    const uint32_t a_row_base = (uint32_t)(wm * 64 + (lg & 1) * 8 + rin);
    const uint32_t b_row_base = (uint32_t)(wn * 64 + (lg >> 1) * 8 + rin);
    const uint32_t a_jbase = (uint32_t)(lg >> 1);
    const uint32_t b_jbase = (uint32_t)(lg & 1);

    float c[4][8][4];
    #pragma unroll
    for (int i = 0; i < 4; ++i)
        #pragma unroll
        for (int j = 0; j < 8; ++j)
            #pragma unroll
            for (int q = 0; q < 4; ++q) c[i][j][q] = 0.0f;

    auto load_chunk = [&](int k, int s) {
        const uint32_t stage = sbase + (uint32_t)s * STAGE_BYTES;
        const size_t k0 = (size_t)k * KCHUNK;
        #pragma unroll
        for (int i = 0; i < 4; ++i) {
            int row = ld_row_a + i * 32;
            uint32_t off = (uint32_t)(row * 128 + ld_j * 16);
            const __half* src = g_A + (size_t)(m0 + row) * KDIM + k0 + ld_j * 8;
            CP_ASYNC16(stage + SW128(off), src);
        }
        #pragma unroll
        for (int i = 0; i < 8; ++i) {
            int row = ld_row_a + i * 32;
            uint32_t off = (uint32_t)(row * 128 + ld_j * 16);
            const __half* src = g_W + (size_t)(n0 + row) * KDIM + k0 + ld_j * 8;
            CP_ASYNC16(stage + A_STAGE_BYTES + SW128(off), src);
        }
    };

    // fragment buffers (persist across chunk boundary)
    uint32_t a[2][4][4], b[2][8][2];

    auto load_frags = [&](uint32_t sA, uint32_t sB, int kk, int buf) {
        #pragma unroll
        for (int sm = 0; sm < 4; ++sm) {
            uint32_t row = a_row_base + sm * 16;
            uint32_t j = a_jbase + kk * 2;
            uint32_t addr = sA + row * 128 + (((j ^ (row & 7)) & 7) << 4);
            LDSM_X4(a[buf][sm][0], a[buf][sm][1], a[buf][sm][2], a[buf][sm][3], addr);
        }
        #pragma unroll
        for (int sn2 = 0; sn2 < 4; ++sn2) {
            uint32_t row = b_row_base + sn2 * 16;
            uint32_t j = b_jbase + kk * 2;
            uint32_t addr = sB + row * 128 + (((j ^ (row & 7)) & 7) << 4);
            uint32_t r0, r1, r2, r3;
            LDSM_X4(r0, r1, r2, r3, addr);
            b[buf][sn2 * 2][0] = r0;     b[buf][sn2 * 2][1] = r1;
            b[buf][sn2 * 2 + 1][0] = r2; b[buf][sn2 * 2 + 1][1] = r3;
        }
    };

    // ---------------- prologue: fill 3 stages, prefetch chunk0 kk0 ----------
    #pragma unroll
    for (int s = 0; s < NSTAGES - 1; ++s) {
        load_chunk(s, s);
        CP_COMMIT();
    }
    CP_WAIT2();            // all but newest 2 done -> chunk 0 resident
    __syncthreads();       // everyone's chunk-0 copies visible
    load_frags(sbase, sbase + A_STAGE_BYTES, 0, 0);

    // ---------------- main loop: sync at tail, head enters MMAs directly ----
    #pragma unroll 1
    for (int k = 0; k < NCHUNKS; ++k) {
        const uint32_t sA = sbase + (uint32_t)(k & 3) * STAGE_BYTES;
        const uint32_t sB = sA + A_STAGE_BYTES;

        #pragma unroll
        for (int kk = 0; kk < 4; ++kk) {
            const int cur = kk & 1;
            if (kk < 3) {
                load_frags(sA, sB, kk + 1, cur ^ 1);
            } else if (k + 1 < NCHUNKS) {
                // tail: chunk k+1 is 2 commits old -> wait is instant
                CP_WAIT1();          // all but newest group done -> k+1 resident
                __syncthreads();     // RAW (stage k+1) + WAR (stage (k-1)&3)
                if (k + NSTAGES - 1 < NCHUNKS)
                    load_chunk(k + NSTAGES - 1, (k + NSTAGES - 1) & 3);
                CP_COMMIT();         // empty near end: keeps wait parity exact
                // prefetch next chunk's kk=0 frags; hidden under kk=3 MMAs
                const uint32_t sAn = sbase + (uint32_t)((k + 1) & 3) * STAGE_BYTES;
                load_frags(sAn, sAn + A_STAGE_BYTES, 0, cur ^ 1);
            }
            #pragma unroll
            for (int sm = 0; sm < 4; ++sm)
                #pragma unroll
                for (int sn = 0; sn < 8; ++sn)
                    MMA16816(c[sm][sn],
                             a[cur][sm][0], a[cur][sm][1], a[cur][sm][2], a[cur][sm][3],
                             b[cur][sn][0], b[cur][sn][1]);
        }
    }

    // ---------------- epilogue ----------------
    const int col_q = 2 * (lane & 3);
    const int row_q = lane >> 2;
    float2 sc[8], bi[8];
    #pragma unroll
    for (int sn = 0; sn < 8; ++sn) {
        const int col = n0 + wn * 64 + sn * 8 + col_q;
        sc[sn] = *reinterpret_cast<const float2*>(w_scale + col);
        bi[sn] = *reinterpret_cast<const float2*>(bias + col);
    }
    #pragma unroll
    for (int sm = 0; sm < 4; ++sm) {
        const int row0 = m0 + wm * 64 + sm * 16 + row_q;
        const int row1 = row0 + 8;
        #pragma unroll
        for (int sn = 0; sn < 8; ++sn) {
            const int col = n0 + wn * 64 + sn * 8 + col_q;
            float y0 = fmaf(c[sm][sn][0], sc[sn].x, bi[sn].x);
            float y1 = fmaf(c[sm][sn][1], sc[sn].y, bi[sn].y);
            float y2 = fmaf(c[sm][sn][2], sc[sn].x, bi[sn].x);
            float y3 = fmaf(c[sm][sn][3], sc[sn].y, bi[sn].y);
            float2 v0 = make_float2(gelu_f(y0), gelu_f(y1));
            float2 v1 = make_float2(gelu_f(y2), gelu_f(y3));
            *reinterpret_cast<float2*>(out + (size_t)row0 * NDIM + col) = v0;
            *reinterpret_cast<float2*>(out + (size_t)row1 * NDIM + col) = v1;
        }
    }
}

// ---------------------------------------------------------------------------
extern "C" void kernel_launch(void* const* d_in, const int* in_sizes, int n_in,
                              void* d_out, int out_size) {
    (void)in_sizes; (void)n_in; (void)out_size;
    const float* hs = (const float*)d_in[0];
    const int* w_int8 = (const int*)d_in[1];
    const float* w_scale = (const float*)d_in[2];
    const float* bias = (const float*)d_in[3];
    float* out = (float*)d_out;

    cudaFuncSetAttribute(gemm_kernel,
                         cudaFuncAttributeMaxDynamicSharedMemorySize, SMEM_TOTAL);

    cvt_kernel<<<GRID_A + GRID_W, 256>>>(hs, w_int8);
    gemm_kernel<<<GRID, 256, SMEM_TOTAL>>>(w_scale, bias, out);
}

// round 7
// speedup vs baseline: 1.1641x; 1.1219x over previous
#include <cuda_runtime.h>
#include <cuda_fp16.h>
#include <cstdint>

// ============================================================================
// out[b,s,o] = gelu_tanh( (hs[b,s,:] . w_int8[o,:]) * w_scale[o] + bias[o] )
// sm_103 (no 'a') PTX target -> tcgen05 unavailable; mma.sync.m16n8k16 path.
//   Prepass (single kernel): A f32->f16, W i32->f16 (exact) into device globals.
//   GEMM: tile 128x256xK64, 4-stage cp.async, tail-positioned sync.
//   R6: 512 threads / 16 warps (4m x 4n, warp tile 32x64) -> 4 warps/SMSP to
//   feed the tensor pipe (R5 profile: 2 warps/SMSP starved issue, tensor=59%).
// ============================================================================

static constexpr int MDIM = 8192;
static constexpr int KDIM = 4096;
static constexpr int NDIM = 16384;
static constexpr int TILE_M = 128;
static constexpr int TILE_N = 256;
static constexpr int KCHUNK = 64;                 // 128 bytes/row = SW128 atom
static constexpr int NCHUNKS = KDIM / KCHUNK;     // 64
static constexpr int NSTAGES = 4;
static constexpr uint32_t A_STAGE_BYTES = TILE_M * 128;   // 16384
static constexpr uint32_t B_STAGE_BYTES = TILE_N * 128;   // 32768
static constexpr uint32_t STAGE_BYTES = A_STAGE_BYTES + B_STAGE_BYTES; // 49152
static constexpr uint32_t SMEM_TOTAL = NSTAGES * STAGE_BYTES;          // 196608

static constexpr int NT_M = MDIM / TILE_M;  // 64
static constexpr int NT_N = NDIM / TILE_N;  // 64
static constexpr int GRID = NT_M * NT_N;    // 4096
static constexpr int GM = 16;               // M-supertile for L2 reuse

static constexpr int NTHREADS = 512;

__device__ __align__(1024) __half g_A[(size_t)MDIM * KDIM];   // 64 MB
__device__ __align__(1024) __half g_W[(size_t)NDIM * KDIM];   // 128 MB

// ---------------------------------------------------------------------------
__device__ __forceinline__ uint32_t smem_u32(const void* p) {
    uint32_t a;
    asm("{ .reg .u64 t; cvta.to.shared.u64 t, %1; cvt.u32.u64 %0, t; }"
        : "=r"(a) : "l"(p));
    return a;
}

#define SW128(o) ((o) ^ (((o) >> 3) & 0x70))

#define CP_ASYNC16(saddr, gaddr) \
    asm volatile("cp.async.cg.shared.global [%0], [%1], 16;" :: "r"(saddr), "l"(gaddr))
#define CP_COMMIT() asm volatile("cp.async.commit_group;" ::: "memory")
#define CP_WAIT2()  asm volatile("cp.async.wait_group 2;" ::: "memory")
#define CP_WAIT1()  asm volatile("cp.async.wait_group 1;" ::: "memory")

#define LDSM_X4(r0, r1, r2, r3, addr)                                          \
    asm volatile("ldmatrix.sync.aligned.m8n8.x4.shared.b16 {%0,%1,%2,%3}, [%4];" \
        : "=r"(r0), "=r"(r1), "=r"(r2), "=r"(r3) : "r"(addr))

#define MMA16816(c, a0, a1, a2, a3, b0, b1)                                    \
    asm volatile("mma.sync.aligned.m16n8k16.row.col.f32.f16.f16.f32 "          \
        "{%0,%1,%2,%3}, {%4,%5,%6,%7}, {%8,%9}, {%0,%1,%2,%3};"                \
        : "+f"((c)[0]), "+f"((c)[1]), "+f"((c)[2]), "+f"((c)[3])               \
        : "r"(a0), "r"(a1), "r"(a2), "r"(a3), "r"(b0), "r"(b1))

// ---------------------------------------------------------------------------
// Merged prepass: blocks [0, GRID_A) convert A, rest convert W.
// ---------------------------------------------------------------------------
static constexpr unsigned GRID_A = (unsigned)((size_t)MDIM * KDIM / 8 / 256);  // 16384
static constexpr unsigned GRID_W = (unsigned)((size_t)NDIM * KDIM / 8 / 256);  // 32768

__global__ void __launch_bounds__(256) cvt_kernel(const float* __restrict__ a_in,
                                                  const int* __restrict__ w_in) {
    if (blockIdx.x < GRID_A) {
        size_t i = ((size_t)blockIdx.x * 256 + threadIdx.x) * 8;
        float4 f0 = *reinterpret_cast<const float4*>(a_in + i);
        float4 f1 = *reinterpret_cast<const float4*>(a_in + i + 4);
        __half2 h[4];
        h[0] = __floats2half2_rn(f0.x, f0.y);
        h[1] = __floats2half2_rn(f0.z, f0.w);
        h[2] = __floats2half2_rn(f1.x, f1.y);
        h[3] = __floats2half2_rn(f1.z, f1.w);
        *reinterpret_cast<uint4*>(g_A + i) = *reinterpret_cast<uint4*>(h);
    } else {
        size_t i = ((size_t)(blockIdx.x - GRID_A) * 256 + threadIdx.x) * 8;
        int4 w0 = *reinterpret_cast<const int4*>(w_in + i);
        int4 w1 = *reinterpret_cast<const int4*>(w_in + i + 4);
        __half2 h[4];
        h[0] = __halves2half2(__int2half_rn(w0.x), __int2half_rn(w0.y));
        h[1] = __halves2half2(__int2half_rn(w0.z), __int2half_rn(w0.w));
        h[2] = __halves2half2(__int2half_rn(w1.x), __int2half_rn(w1.y));
        h[3] = __halves2half2(__int2half_rn(w1.z), __int2half_rn(w1.w));
        *reinterpret_cast<uint4*>(g_W + i) = *reinterpret_cast<uint4*>(h);
    }
}

__device__ __forceinline__ float tanh_ex(float x) {
    return 1.0f - 2.0f / (1.0f + __expf(2.0f * x));
}
__device__ __forceinline__ float gelu_f(float y) {
    float inner = 0.7978845608028654f * fmaf(0.044715f * y * y, y, y);
    return 0.5f * y * (1.0f + tanh_ex(inner));
}

// ---------------------------------------------------------------------------
// GEMM kernel: 512 threads, warp grid 4(m) x 4(n), warp tile 32x64
// ---------------------------------------------------------------------------
__global__ void __launch_bounds__(NTHREADS, 1) gemm_kernel(
    const float* __restrict__ w_scale,
    const float* __restrict__ bias,
    float* __restrict__ out
) {
    extern __shared__ __align__(1024) char smem[];
    const uint32_t sbase = smem_u32(smem);
    const int tid = threadIdx.x;
    const int lane = tid & 31;
    const int wid = tid >> 5;
    const int wm = wid >> 2;        // 0..3 -> m offset wm*32
    const int wn = wid & 3;         // 0..3 -> n offset wn*64

    // Supertiled rasterization for L2 reuse
    const int bid = blockIdx.x;
    const int tpg = GM * NT_N;
    const int g = bid / tpg;
    const int r = bid % tpg;
    const int mi = g * GM + (r % GM);
    const int ni = r / GM;
    const int m0 = mi * TILE_M;
    const int n0 = ni * TILE_N;

    const int ld_row = tid >> 3;            // 0..63
    const int ld_j = tid & 7;               // 16B seg within 128B row
    const int lg = lane >> 3;               // ldmatrix group 0..3
    const int rin = lane & 7;

    // fragment smem addressing (layout verified R3-R5)
    const uint32_t a_row_base = (uint32_t)(wm * 32 + (lg & 1) * 8 + rin);
    const uint32_t b_row_base = (uint32_t)(wn * 64 + (lg >> 1) * 8 + rin);
    const uint32_t a_jbase = (uint32_t)(lg >> 1);
    const uint32_t b_jbase = (uint32_t)(lg & 1);

    float c[2][8][4];
    #pragma unroll
    for (int i = 0; i < 2; ++i)
        #pragma unroll
        for (int j = 0; j < 8; ++j)
            #pragma unroll
            for (int q = 0; q < 4; ++q) c[i][j][q] = 0.0f;

    auto load_chunk = [&](int k, int s) {
        const uint32_t stage = sbase + (uint32_t)s * STAGE_BYTES;
        const size_t k0 = (size_t)k * KCHUNK;
        #pragma unroll
        for (int i = 0; i < 2; ++i) {
            int row = ld_row + i * 64;
            uint32_t off = (uint32_t)(row * 128 + ld_j * 16);
            const __half* src = g_A + (size_t)(m0 + row) * KDIM + k0 + ld_j * 8;
            CP_ASYNC16(stage + SW128(off), src);
        }
        #pragma unroll
        for (int i = 0; i < 4; ++i) {
            int row = ld_row + i * 64;
            uint32_t off = (uint32_t)(row * 128 + ld_j * 16);
            const __half* src = g_W + (size_t)(n0 + row) * KDIM + k0 + ld_j * 8;
            CP_ASYNC16(stage + A_STAGE_BYTES + SW128(off), src);
        }
    };

    // fragment buffers (persist across chunk boundary)
    uint32_t a[2][2][4], b[2][8][2];

    auto load_frags = [&](uint32_t sA, uint32_t sB, int kk, int buf) {
        #pragma unroll
        for (int sm = 0; sm < 2; ++sm) {
            uint32_t row = a_row_base + sm * 16;
            uint32_t j = a_jbase + kk * 2;
            uint32_t addr = sA + row * 128 + (((j ^ (row & 7)) & 7) << 4);
            LDSM_X4(a[buf][sm][0], a[buf][sm][1], a[buf][sm][2], a[buf][sm][3], addr);
        }
        #pragma unroll
        for (int sn2 = 0; sn2 < 4; ++sn2) {
            uint32_t row = b_row_base + sn2 * 16;
            uint32_t j = b_jbase + kk * 2;
            uint32_t addr = sB + row * 128 + (((j ^ (row & 7)) & 7) << 4);
            uint32_t r0, r1, r2, r3;
            LDSM_X4(r0, r1, r2, r3, addr);
            b[buf][sn2 * 2][0] = r0;     b[buf][sn2 * 2][1] = r1;
            b[buf][sn2 * 2 + 1][0] = r2; b[buf][sn2 * 2 + 1][1] = r3;
        }
    };

    // ---------------- prologue: fill 3 stages, prefetch chunk0 kk0 ----------
    #pragma unroll
    for (int s = 0; s < NSTAGES - 1; ++s) {
        load_chunk(s, s);
        CP_COMMIT();
    }
    CP_WAIT2();            // all but newest 2 done -> chunk 0 resident
    __syncthreads();       // everyone's chunk-0 copies visible
    load_frags(sbase, sbase + A_STAGE_BYTES, 0, 0);

    // ---------------- main loop: sync at tail ----------------
    #pragma unroll 1
    for (int k = 0; k < NCHUNKS; ++k) {
        const uint32_t sA = sbase + (uint32_t)(k & 3) * STAGE_BYTES;
        const uint32_t sB = sA + A_STAGE_BYTES;

        #pragma unroll
        for (int kk = 0; kk < 4; ++kk) {
            const int cur = kk & 1;
            if (kk < 3) {
                load_frags(sA, sB, kk + 1, cur ^ 1);
            } else if (k + 1 < NCHUNKS) {
                CP_WAIT1();          // chunk k+1 resident (committed 2 iters ago)
                __syncthreads();     // RAW (stage k+1) + WAR (stage (k-1)&3)
                if (k + NSTAGES - 1 < NCHUNKS)
                    load_chunk(k + NSTAGES - 1, (k + NSTAGES - 1) & 3);
                CP_COMMIT();         // keep wait-group parity exact
                const uint32_t sAn = sbase + (uint32_t)((k + 1) & 3) * STAGE_BYTES;
                load_frags(sAn, sAn + A_STAGE_BYTES, 0, cur ^ 1);
            }
            #pragma unroll
            for (int sm = 0; sm < 2; ++sm)
                #pragma unroll
                for (int sn = 0; sn < 8; ++sn)
                    MMA16816(c[sm][sn],
                             a[cur][sm][0], a[cur][sm][1], a[cur][sm][2], a[cur][sm][3],
                             b[cur][sn][0], b[cur][sn][1]);
        }
    }

    // ---------------- epilogue ----------------
    const int col_q = 2 * (lane & 3);
    const int row_q = lane >> 2;
    float2 sc[8], bi[8];
    #pragma unroll
    for (int sn = 0; sn < 8; ++sn) {
        const int col = n0 + wn * 64 + sn * 8 + col_q;
        sc[sn] = *reinterpret_cast<const float2*>(w_scale + col);
        bi[sn] = *reinterpret_cast<const float2*>(bias + col);
    }
    #pragma unroll
    for (int sm = 0; sm < 2; ++sm) {
        const int row0 = m0 + wm * 32 + sm * 16 + row_q;
        const int row1 = row0 + 8;
        #pragma unroll
        for (int sn = 0; sn < 8; ++sn) {
            const int col = n0 + wn * 64 + sn * 8 + col_q;
            float y0 = fmaf(c[sm][sn][0], sc[sn].x, bi[sn].x);
            float y1 = fmaf(c[sm][sn][1], sc[sn].y, bi[sn].y);
            float y2 = fmaf(c[sm][sn][2], sc[sn].x, bi[sn].x);
            float y3 = fmaf(c[sm][sn][3], sc[sn].y, bi[sn].y);
            float2 v0 = make_float2(gelu_f(y0), gelu_f(y1));
            float2 v1 = make_float2(gelu_f(y2), gelu_f(y3));
            *reinterpret_cast<float2*>(out + (size_t)row0 * NDIM + col) = v0;
            *reinterpret_cast<float2*>(out + (size_t)row1 * NDIM + col) = v1;
        }
    }
}

// ---------------------------------------------------------------------------
extern "C" void kernel_launch(void* const* d_in, const int* in_sizes, int n_in,
                              void* d_out, int out_size) {
    (void)in_sizes; (void)n_in; (void)out_size;
    const float* hs = (const float*)d_in[0];
    const int* w_int8 = (const int*)d_in[1];
    const float* w_scale = (const float*)d_in[2];
    const float* bias = (const float*)d_in[3];
    float* out = (float*)d_out;

    cudaFuncSetAttribute(gemm_kernel,
                         cudaFuncAttributeMaxDynamicSharedMemorySize, SMEM_TOTAL);

    cvt_kernel<<<GRID_A + GRID_W, 256>>>(hs, w_int8);
    gemm_kernel<<<GRID, NTHREADS, SMEM_TOTAL>>>(w_scale, bias, out);
}

// round 8
// speedup vs baseline: 1.2287x; 1.0555x over previous
#include <cuda_runtime.h>
#include <cuda_fp16.h>
#include <cstdint>

// ============================================================================
// out[b,s,o] = gelu_tanh( (hs[b,s,:] . w_int8[o,:]) * w_scale[o] + bias[o] )
// sm_103 (no 'a') PTX target -> tcgen05 unavailable; mma.sync.m16n8k16 path.
//   Prepass: A f32->f16, W i32->f16 (exact) into device globals.
//   GEMM: tile 128x256, 16 warps (4m x 4n, warp tile 32x64).
//   R7: 2-stage x 98KB superchunks (K=128/stage as 2 sub-tiles), 32 barriers
//   (was 64), wait_group(0) boundary, 8 phases/barrier for warp drift to
//   smooth LDSM crossbar bursts. Tail-sync + cross-boundary frag prefetch.
// ============================================================================

static constexpr int MDIM = 8192;
static constexpr int KDIM = 4096;
static constexpr int NDIM = 16384;
static constexpr int TILE_M = 128;
static constexpr int TILE_N = 256;
static constexpr int KSUPER = 128;                // per stage (2 x 64 sub-tiles)
static constexpr int NSUPER = KDIM / KSUPER;      // 32
static constexpr uint32_t A_SUB_BYTES = TILE_M * 128;     // 16384
static constexpr uint32_t B_SUB_BYTES = TILE_N * 128;     // 32768
static constexpr uint32_t SUB_BYTES = A_SUB_BYTES + B_SUB_BYTES;  // 49152
static constexpr uint32_t STAGE_BYTES = 2 * SUB_BYTES;            // 98304
static constexpr uint32_t SMEM_TOTAL = 2 * STAGE_BYTES;           // 196608

static constexpr int NT_M = MDIM / TILE_M;  // 64
static constexpr int NT_N = NDIM / TILE_N;  // 64
static constexpr int GRID = NT_M * NT_N;    // 4096
static constexpr int GM = 16;               // M-supertile for L2 reuse

static constexpr int NTHREADS = 512;

__device__ __align__(1024) __half g_A[(size_t)MDIM * KDIM];   // 64 MB
__device__ __align__(1024) __half g_W[(size_t)NDIM * KDIM];   // 128 MB

// ---------------------------------------------------------------------------
__device__ __forceinline__ uint32_t smem_u32(const void* p) {
    uint32_t a;
    asm("{ .reg .u64 t; cvta.to.shared.u64 t, %1; cvt.u32.u64 %0, t; }"
        : "=r"(a) : "l"(p));
    return a;
}

#define SW128(o) ((o) ^ (((o) >> 3) & 0x70))

#define CP_ASYNC16(saddr, gaddr) \
    asm volatile("cp.async.cg.shared.global [%0], [%1], 16;" :: "r"(saddr), "l"(gaddr))
#define CP_COMMIT() asm volatile("cp.async.commit_group;" ::: "memory")
#define CP_WAIT0()  asm volatile("cp.async.wait_group 0;" ::: "memory")
#define CP_WAIT1()  asm volatile("cp.async.wait_group 1;" ::: "memory")

#define LDSM_X4(r0, r1, r2, r3, addr)                                          \
    asm volatile("ldmatrix.sync.aligned.m8n8.x4.shared.b16 {%0,%1,%2,%3}, [%4];" \
        : "=r"(r0), "=r"(r1), "=r"(r2), "=r"(r3) : "r"(addr))

#define MMA16816(c, a0, a1, a2, a3, b0, b1)                                    \
    asm volatile("mma.sync.aligned.m16n8k16.row.col.f32.f16.f16.f32 "          \
        "{%0,%1,%2,%3}, {%4,%5,%6,%7}, {%8,%9}, {%0,%1,%2,%3};"                \
        : "+f"((c)[0]), "+f"((c)[1]), "+f"((c)[2]), "+f"((c)[3])               \
        : "r"(a0), "r"(a1), "r"(a2), "r"(a3), "r"(b0), "r"(b1))

// ---------------------------------------------------------------------------
// Merged prepass: blocks [0, GRID_A) convert A, rest convert W.
// ---------------------------------------------------------------------------
static constexpr unsigned GRID_A = (unsigned)((size_t)MDIM * KDIM / 8 / 256);  // 16384
static constexpr unsigned GRID_W = (unsigned)((size_t)NDIM * KDIM / 8 / 256);  // 32768

__global__ void __launch_bounds__(256) cvt_kernel(const float* __restrict__ a_in,
                                                  const int* __restrict__ w_in) {
    if (blockIdx.x < GRID_A) {
        size_t i = ((size_t)blockIdx.x * 256 + threadIdx.x) * 8;
        float4 f0 = *reinterpret_cast<const float4*>(a_in + i);
        float4 f1 = *reinterpret_cast<const float4*>(a_in + i + 4);
        __half2 h[4];
        h[0] = __floats2half2_rn(f0.x, f0.y);
        h[1] = __floats2half2_rn(f0.z, f0.w);
        h[2] = __floats2half2_rn(f1.x, f1.y);
        h[3] = __floats2half2_rn(f1.z, f1.w);
        *reinterpret_cast<uint4*>(g_A + i) = *reinterpret_cast<uint4*>(h);
    } else {
        size_t i = ((size_t)(blockIdx.x - GRID_A) * 256 + threadIdx.x) * 8;
        int4 w0 = *reinterpret_cast<const int4*>(w_in + i);
        int4 w1 = *reinterpret_cast<const int4*>(w_in + i + 4);
        __half2 h[4];
        h[0] = __halves2half2(__int2half_rn(w0.x), __int2half_rn(w0.y));
        h[1] = __halves2half2(__int2half_rn(w0.z), __int2half_rn(w0.w));
        h[2] = __halves2half2(__int2half_rn(w1.x), __int2half_rn(w1.y));
        h[3] = __halves2half2(__int2half_rn(w1.z), __int2half_rn(w1.w));
        *reinterpret_cast<uint4*>(g_W + i) = *reinterpret_cast<uint4*>(h);
    }
}

__device__ __forceinline__ float tanh_ex(float x) {
    return 1.0f - 2.0f / (1.0f + __expf(2.0f * x));
}
__device__ __forceinline__ float gelu_f(float y) {
    float inner = 0.7978845608028654f * fmaf(0.044715f * y * y, y, y);
    return 0.5f * y * (1.0f + tanh_ex(inner));
}

// ---------------------------------------------------------------------------
// GEMM kernel: 512 threads, warp grid 4(m) x 4(n), warp tile 32x64
// ---------------------------------------------------------------------------
__global__ void __launch_bounds__(NTHREADS, 1) gemm_kernel(
    const float* __restrict__ w_scale,
    const float* __restrict__ bias,
    float* __restrict__ out
) {
    extern __shared__ __align__(1024) char smem[];
    const uint32_t sbase = smem_u32(smem);
    const int tid = threadIdx.x;
    const int lane = tid & 31;
    const int wid = tid >> 5;
    const int wm = wid >> 2;        // 0..3 -> m offset wm*32
    const int wn = wid & 3;         // 0..3 -> n offset wn*64

    // Supertiled rasterization for L2 reuse
    const int bid = blockIdx.x;
    const int tpg = GM * NT_N;
    const int g = bid / tpg;
    const int r = bid % tpg;
    const int mi = g * GM + (r % GM);
    const int ni = r / GM;
    const int m0 = mi * TILE_M;
    const int n0 = ni * TILE_N;

    const int ld_row = tid >> 3;            // 0..63
    const int ld_j = tid & 7;               // 16B seg within 128B row
    const int lg = lane >> 3;               // ldmatrix group 0..3
    const int rin = lane & 7;

    // fragment smem addressing (layout verified R3-R6)
    const uint32_t a_row_base = (uint32_t)(wm * 32 + (lg & 1) * 8 + rin);
    const uint32_t b_row_base = (uint32_t)(wn * 64 + (lg >> 1) * 8 + rin);
    const uint32_t a_jbase = (uint32_t)(lg >> 1);
    const uint32_t b_jbase = (uint32_t)(lg & 1);

    float c[2][8][4];
    #pragma unroll
    for (int i = 0; i < 2; ++i)
        #pragma unroll
        for (int j = 0; j < 8; ++j)
            #pragma unroll
            for (int q = 0; q < 4; ++q) c[i][j][q] = 0.0f;

    // Load one superchunk (K=128 = 2 sub-tiles of 64) into stage s.
    auto load_super = [&](int k, int s) {
        const uint32_t stage = sbase + (uint32_t)s * STAGE_BYTES;
        #pragma unroll
        for (int sub = 0; sub < 2; ++sub) {
            const uint32_t base = stage + (uint32_t)sub * SUB_BYTES;
            const size_t k0 = (size_t)k * KSUPER + sub * 64;
            #pragma unroll
            for (int i = 0; i < 2; ++i) {
                int row = ld_row + i * 64;
                uint32_t off = (uint32_t)(row * 128 + ld_j * 16);
                const __half* src = g_A + (size_t)(m0 + row) * KDIM + k0 + ld_j * 8;
                CP_ASYNC16(base + SW128(off), src);
            }
            #pragma unroll
            for (int i = 0; i < 4; ++i) {
                int row = ld_row + i * 64;
                uint32_t off = (uint32_t)(row * 128 + ld_j * 16);
                const __half* src = g_W + (size_t)(n0 + row) * KDIM + k0 + ld_j * 8;
                CP_ASYNC16(base + A_SUB_BYTES + SW128(off), src);
            }
        }
    };

    // fragment buffers (persist across superchunk boundary)
    uint32_t a[2][2][4], b[2][8][2];

    // phase p in 0..7: sub = p>>2, kk = p&3
    auto load_frags = [&](uint32_t stage, int p, int buf) {
        const uint32_t sA = stage + (uint32_t)(p >> 2) * SUB_BYTES;
        const uint32_t sB = sA + A_SUB_BYTES;
        const int kk = p & 3;
        #pragma unroll
        for (int sm = 0; sm < 2; ++sm) {
            uint32_t row = a_row_base + sm * 16;
            uint32_t j = a_jbase + kk * 2;
            uint32_t addr = sA + row * 128 + (((j ^ (row & 7)) & 7) << 4);
            LDSM_X4(a[buf][sm][0], a[buf][sm][1], a[buf][sm][2], a[buf][sm][3], addr);
        }
        #pragma unroll
        for (int sn2 = 0; sn2 < 4; ++sn2) {
            uint32_t row = b_row_base + sn2 * 16;
            uint32_t j = b_jbase + kk * 2;
            uint32_t addr = sB + row * 128 + (((j ^ (row & 7)) & 7) << 4);
            uint32_t r0, r1, r2, r3;
            LDSM_X4(r0, r1, r2, r3, addr);
            b[buf][sn2 * 2][0] = r0;     b[buf][sn2 * 2][1] = r1;
            b[buf][sn2 * 2 + 1][0] = r2; b[buf][sn2 * 2 + 1][1] = r3;
        }
    };

    // ---------------- prologue: 2 superchunks in flight ----------------
    load_super(0, 0);
    CP_COMMIT();
    load_super(1, 1);
    CP_COMMIT();
    CP_WAIT1();            // superchunk 0 resident
    __syncthreads();
    load_frags(sbase, 0, 0);

    // ---------------- main loop: one barrier per superchunk ----------------
    #pragma unroll 1
    for (int k = 0; k < NSUPER; ++k) {
        const uint32_t stage = sbase + (uint32_t)(k & 1) * STAGE_BYTES;

        #pragma unroll
        for (int p = 0; p < 8; ++p) {
            const int cur = p & 1;
            if (p < 7) {
                load_frags(stage, p + 1, cur ^ 1);
            } else if (k + 1 < NSUPER) {
                CP_WAIT0();          // superchunk k+1 resident (issued 1 super ago)
                __syncthreads();     // RAW (stage k+1) + WAR (reuse stage k&1)
                if (k + 2 < NSUPER) {
                    load_super(k + 2, k & 1);
                    CP_COMMIT();
                }
                const uint32_t stn = sbase + (uint32_t)((k + 1) & 1) * STAGE_BYTES;
                load_frags(stn, 0, cur ^ 1);   // hidden under phase-7 MMAs
            }
            #pragma unroll
            for (int sm = 0; sm < 2; ++sm)
                #pragma unroll
                for (int sn = 0; sn < 8; ++sn)
                    MMA16816(c[sm][sn],
                             a[cur][sm][0], a[cur][sm][1], a[cur][sm][2], a[cur][sm][3],
                             b[cur][sn][0], b[cur][sn][1]);
        }
    }

    // ---------------- epilogue ----------------
    const int col_q = 2 * (lane & 3);
    const int row_q = lane >> 2;
    float2 sc[8], bi[8];
    #pragma unroll
    for (int sn = 0; sn < 8; ++sn) {
        const int col = n0 + wn * 64 + sn * 8 + col_q;
        sc[sn] = *reinterpret_cast<const float2*>(w_scale + col);
        bi[sn] = *reinterpret_cast<const float2*>(bias + col);
    }
    #pragma unroll
    for (int sm = 0; sm < 2; ++sm) {
        const int row0 = m0 + wm * 32 + sm * 16 + row_q;
        const int row1 = row0 + 8;
        #pragma unroll
        for (int sn = 0; sn < 8; ++sn) {
            const int col = n0 + wn * 64 + sn * 8 + col_q;
            float y0 = fmaf(c[sm][sn][0], sc[sn].x, bi[sn].x);
            float y1 = fmaf(c[sm][sn][1], sc[sn].y, bi[sn].y);
            float y2 = fmaf(c[sm][sn][2], sc[sn].x, bi[sn].x);
            float y3 = fmaf(c[sm][sn][3], sc[sn].y, bi[sn].y);
            float2 v0 = make_float2(gelu_f(y0), gelu_f(y1));
            float2 v1 = make_float2(gelu_f(y2), gelu_f(y3));
            *reinterpret_cast<float2*>(out + (size_t)row0 * NDIM + col) = v0;
            *reinterpret_cast<float2*>(out + (size_t)row1 * NDIM + col) = v1;
        }
    }
}

// ---------------------------------------------------------------------------
extern "C" void kernel_launch(void* const* d_in, const int* in_sizes, int n_in,
                              void* d_out, int out_size) {
    (void)in_sizes; (void)n_in; (void)out_size;
    const float* hs = (const float*)d_in[0];
    const int* w_int8 = (const int*)d_in[1];
    const float* w_scale = (const float*)d_in[2];
    const float* bias = (const float*)d_in[3];
    float* out = (float*)d_out;

    cudaFuncSetAttribute(gemm_kernel,
                         cudaFuncAttributeMaxDynamicSharedMemorySize, SMEM_TOTAL);

    cvt_kernel<<<GRID_A + GRID_W, 256>>>(hs, w_int8);
    gemm_kernel<<<GRID, NTHREADS, SMEM_TOTAL>>>(w_scale, bias, out);
}